// round 6
// baseline (speedup 1.0000x reference)
#include <cuda_runtime.h>
#include <cstddef>

#define FULLMASK 0xffffffffu
typedef unsigned long long u64;

// T=128, D=768, HID=768, L=3, OUT=768, LH=2304
__device__ float g_H[128 * 2304];        // h_cat per step
__device__ float g_wfT[2304 * 768];      // transposed w_final
__device__ float g_part[12 * 128 * 768]; // split-K partials

// ---------------------------------------------------------------- helpers
__device__ __forceinline__ unsigned smem_u32(const void* p) {
    unsigned a;
    asm("{ .reg .u64 t; cvta.to.shared.u64 t, %1; cvt.u32.u64 %0, t; }"
        : "=r"(a) : "l"(p));
    return a;
}
__device__ __forceinline__ void cp_async16(unsigned d, const void* src) {
    asm volatile("cp.async.ca.shared.global [%0], [%1], 16;\n" :: "r"(d), "l"(src));
}
__device__ __forceinline__ void cp_commit() { asm volatile("cp.async.commit_group;\n" ::); }
__device__ __forceinline__ void cp_wait0()  { asm volatile("cp.async.wait_group 0;\n" ::); }

__device__ __forceinline__ u64 fma2(u64 a, u64 b, u64 c) {
    u64 d; asm("fma.rn.f32x2 %0, %1, %2, %3;" : "=l"(d) : "l"(a), "l"(b), "l"(c)); return d;
}
__device__ __forceinline__ u64 mul2(u64 a, u64 b) {
    u64 d; asm("mul.rn.f32x2 %0, %1, %2;" : "=l"(d) : "l"(a), "l"(b)); return d;
}
__device__ __forceinline__ u64 pk2(float x, float y) {
    u64 d; asm("mov.b64 %0, {%1, %2};" : "=l"(d) : "f"(x), "f"(y)); return d;
}
__device__ __forceinline__ float2 up2(u64 v) {
    float2 r; asm("mov.b64 {%0, %1}, %2;" : "=f"(r.x), "=f"(r.y) : "l"(v)); return r;
}
__device__ __forceinline__ void lds2(u64& a, u64& b, unsigned addr) {
    asm volatile("ld.shared.v2.b64 {%0, %1}, [%2];" : "=l"(a), "=l"(b) : "r"(addr));
}
__device__ __forceinline__ void ldg2(u64& a, u64& b, const float* p) {
    asm volatile("ld.global.nc.v2.b64 {%0, %1}, [%2];" : "=l"(a), "=l"(b) : "l"(p));
}
__device__ __forceinline__ float sig_fast(float z) {
    float e = __expf(-z);
    return __fdividef(1.0f, 1.0f + e);
}
__device__ __forceinline__ float wredsum(float a) {
#pragma unroll
    for (int m = 16; m >= 1; m >>= 1) a += __shfl_xor_sync(FULLMASK, a, m);
    return a;
}

// ---------------------------------------------------------------- shared memory
struct ScanSmem { float wxb[2048]; __align__(16) float xb[2 * 4 * 768]; };  // 32.7KB
union Smem {
    ScanSmem s;
    float tile[64 * 65];          // transpose prologue
};

// ---------------------------------------------------------------- kernel 1: transpose prologue + scan
// 144 CTAs x 512 threads. CTA j: layer l=j/48, rows [(j%48)*16,+16).
// Warp w owns row w (1 row/warp); lane owns cols {4*lane+128*kk+q : kk<6}.
__global__ void __launch_bounds__(512, 1) k_scan(
    const float* __restrict__ x_seq, const float* __restrict__ W,
    const float* __restrict__ b, const float* __restrict__ lam,
    const float* __restrict__ eta0, const float* __restrict__ eta1p,
    const float* __restrict__ eta2, const float* __restrict__ P_init,
    const float* __restrict__ wf)
{
    __shared__ Smem sm;
    const int tid = threadIdx.x;
    const int bid = blockIdx.x;

    // ---- prologue: wf transpose, 3 tiles of 64x64 per CTA (432 total)
    {
        const int ty = tid >> 4;              // 0..31
        const int tx4 = (tid & 15) * 4;       // 0,4,..,60
#pragma unroll 1
        for (int it = 0; it < 3; it++) {
            const int tt = bid * 3 + it;
            const int o0 = (tt % 12) * 64;
            const int j0 = (tt / 12) * 64;
#pragma unroll
            for (int i = 0; i < 2; i++) {
                int r = ty + 32 * i;
                float4 v = *(const float4*)(wf + (size_t)(o0 + r) * 2304 + j0 + tx4);
                sm.tile[r * 65 + tx4 + 0] = v.x; sm.tile[r * 65 + tx4 + 1] = v.y;
                sm.tile[r * 65 + tx4 + 2] = v.z; sm.tile[r * 65 + tx4 + 3] = v.w;
            }
            __syncthreads();
#pragma unroll
            for (int i = 0; i < 2; i++) {
                int jj = ty + 32 * i;
                float4 v;
                v.x = sm.tile[(tx4 + 0) * 65 + jj];
                v.y = sm.tile[(tx4 + 1) * 65 + jj];
                v.z = sm.tile[(tx4 + 2) * 65 + jj];
                v.w = sm.tile[(tx4 + 3) * 65 + jj];
                *(float4*)(g_wfT + (size_t)(j0 + jj) * 768 + o0 + tx4) = v;
            }
            __syncthreads();
        }
    }

    // ---- scan setup
    const int l  = bid / 48;
    const int rb = (bid % 48) * 16;
    const int w = tid >> 5, lane = tid & 31;
    const int gr = rb + w;                    // this warp's row within layer
    const float* Wl = W + (size_t)l * 589824;
    const int cb = 4 * lane;
    float* wxb = sm.s.wxb;

    // ---- WXB precompute: wxb[t][w] = W[gr,:]@x_t + b[gr]
    {
        u64 wv[12];
#pragma unroll
        for (int kk = 0; kk < 6; kk++)
            ldg2(wv[2 * kk], wv[2 * kk + 1], Wl + (size_t)gr * 768 + cb + 128 * kk);
        const float bb = b[l * 768 + gr];

        float4* xf4 = (float4*)sm.s.xb;
        const float4* xs4 = (const float4*)x_seq;
        const unsigned xfs = smem_u32(sm.s.xb);
        for (int c0 = 0; c0 < 128; c0 += 8) {
#pragma unroll
            for (int i = 0; i < 3; i++)
                xf4[tid + 512 * i] = xs4[(size_t)c0 * 192 + tid + 512 * i];
            __syncthreads();
#pragma unroll
            for (int tt = 0; tt < 8; tt++) {
                const unsigned xa = xfs + tt * 3072 + 16 * lane;
                u64 a0 = 0, a1 = 0, a2 = 0, a3 = 0;
#pragma unroll
                for (int kk = 0; kk < 3; kk++) {
                    u64 x0, x1, x2, x3;
                    lds2(x0, x1, xa + 1024 * kk);
                    lds2(x2, x3, xa + 1024 * kk + 512);
                    a0 = fma2(wv[4 * kk + 0], x0, a0);
                    a1 = fma2(wv[4 * kk + 1], x1, a1);
                    a2 = fma2(wv[4 * kk + 2], x2, a2);
                    a3 = fma2(wv[4 * kk + 3], x3, a3);
                }
                float2 f0 = up2(a0), f1 = up2(a1), f2 = up2(a2), f3 = up2(a3);
                float s = wredsum(((f0.x + f0.y) + (f1.x + f1.y))
                                + ((f2.x + f2.y) + (f3.x + f3.y)));
                if (lane == 0) wxb[(c0 + tt) * 16 + w] = s + bb;
            }
            __syncthreads();
        }
    }

    // ---- persistent state (unified A/M): A: q=P, e=eta, escal=1 | M: q=W.P, e=W, escal=eta1
    u64 q[12], e[12];
    const float* Pl = P_init + (size_t)l * 589824;
#pragma unroll
    for (int kk = 0; kk < 6; kk++)
        ldg2(q[2 * kk], q[2 * kk + 1], Pl + (size_t)gr * 768 + cb + 128 * kk);
    const float* ep = (l == 0) ? eta0 : ((l == 2) ? eta2 : Wl);
#pragma unroll
    for (int kk = 0; kk < 6; kk++)
        ldg2(e[2 * kk], e[2 * kk + 1], ep + (size_t)gr * 768 + cb + 128 * kk);
    if (l == 1) {
#pragma unroll
        for (int k = 0; k < 12; k++) q[k] = mul2(q[k], e[k]);
    }
    const float decay = 1.0f / (1.0f + __expf(-lam[l]));
    const float escal = (l == 1) ? eta1p[0] : 1.0f;
    const float d2v = decay * decay, d3v = d2v * decay, d4v = d2v * d2v;
    float dsc[4], umul[4];
    dsc[0] = 1.f; dsc[1] = decay; dsc[2] = d2v; dsc[3] = d3v;
    umul[0] = escal / decay; umul[1] = escal / d2v;
    umul[2] = escal / d3v;   umul[3] = escal / d4v;
    const u64 d42 = pk2(d4v, d4v);
    const int gc = l * 768 + rb + w;
    const unsigned xbs = smem_u32(sm.s.xb);

    // ---- preload chunk 0 (4 steps = 768 float4)
    {
#pragma unroll
        for (int i = 0; i < 2; i++) {
            int idx = tid + 512 * i;
            if (idx < 768) cp_async16(xbs + 16 * idx, x_seq + 4 * idx);
        }
        cp_commit(); cp_wait0();
    }
    __syncthreads();

    // ---- the scan: 32 chunks x 4 steps, x double-buffered
    for (int c = 0; c < 32; c++) {
        if (c < 31) {
            const float* src = x_seq + (size_t)(c + 1) * 3072;
            unsigned dst = xbs + ((c + 1) & 1) * 12288;
#pragma unroll
            for (int i = 0; i < 2; i++) {
                int idx = tid + 512 * i;
                if (idx < 768) cp_async16(dst + 16 * idx, src + 4 * idx);
            }
            cp_commit();
        }
        const unsigned xcs = xbs + (c & 1) * 12288;
#pragma unroll
        for (int j = 0; j < 4; j++) {
            const int t = c * 4 + j;
            const unsigned xa = xcs + j * 3072 + 16 * lane;
            u64 xv[12];
#pragma unroll
            for (int kk = 0; kk < 6; kk++) lds2(xv[2 * kk], xv[2 * kk + 1], xa + 512 * kk);

            // dot: 12 fma2, 4 accumulators
            u64 a0 = 0, a1 = 0, a2 = 0, a3 = 0;
#pragma unroll
            for (int kk = 0; kk < 3; kk++) {
                a0 = fma2(q[4 * kk + 0], xv[4 * kk + 0], a0);
                a1 = fma2(q[4 * kk + 1], xv[4 * kk + 1], a1);
                a2 = fma2(q[4 * kk + 2], xv[4 * kk + 2], a2);
                a3 = fma2(q[4 * kk + 3], xv[4 * kk + 3], a3);
            }
            float2 f0 = up2(a0), f1 = up2(a1), f2 = up2(a2), f3 = up2(a3);
            float s = wredsum(((f0.x + f0.y) + (f1.x + f1.y))
                            + ((f2.x + f2.y) + (f3.x + f3.y)));
            float h = sig_fast(fmaf(dsc[j], s, wxb[t * 16 + w]));
            if (lane == 0) g_H[(size_t)t * 2304 + gc] = h;

            // update: q += e .* (hh * x)
            float hh = h * umul[j];
            u64 h2 = pk2(hh, hh);
#pragma unroll
            for (int k = 0; k < 12; k++)
                q[k] = fma2(e[k], mul2(h2, xv[k]), q[k]);
        }
        // chunk-end rescale: q holds state/decay^4 -> back to state
#pragma unroll
        for (int k = 0; k < 12; k++) q[k] = mul2(q[k], d42);
        if (c < 31) cp_wait0();
        __syncthreads();
    }
}

// ---------------------------------------------------------------- kernel 2: readout GEMM (split-K 12)
__global__ void __launch_bounds__(256) k_gemm() {
    __shared__ __align__(16) float Hs[192 * 36];  // [192 j][32 t + pad 4]
    const int ob = blockIdx.x, tb = blockIdx.y, kb = blockIdx.z;
    const int tid = threadIdx.x;
    const int t0 = tb * 32;
#pragma unroll
    for (int i = 0; i < 24; i++) {
        int idx = tid + 256 * i;
        int tl = idx / 192, jl = idx - tl * 192;
        Hs[jl * 36 + tl] = g_H[(size_t)(t0 + tl) * 2304 + kb * 192 + jl];
    }
    __syncthreads();

    u64 acc[16];
#pragma unroll
    for (int i = 0; i < 16; i++) acc[i] = 0;

    const int o = ob * 256 + tid;
    const float* wp = g_wfT + (size_t)(kb * 192) * 768 + o;
    const unsigned hs = smem_u32(Hs);
#pragma unroll 8
    for (int j = 0; j < 192; j++) {
        float wv = __ldg(wp + (size_t)j * 768);
        u64 w2 = pk2(wv, wv);
        const unsigned ha = hs + j * 144;
#pragma unroll
        for (int u = 0; u < 8; u++) {
            u64 h0, h1; lds2(h0, h1, ha + 16 * u);
            acc[2 * u]     = fma2(w2, h0, acc[2 * u]);
            acc[2 * u + 1] = fma2(w2, h1, acc[2 * u + 1]);
        }
    }
    float* pp = g_part + (size_t)kb * 98304 + (size_t)t0 * 768 + o;
#pragma unroll
    for (int u = 0; u < 8; u++) {
        float2 v0 = up2(acc[2 * u]), v1 = up2(acc[2 * u + 1]);
        pp[(size_t)(4 * u + 0) * 768] = v0.x;
        pp[(size_t)(4 * u + 1) * 768] = v0.y;
        pp[(size_t)(4 * u + 2) * 768] = v1.x;
        pp[(size_t)(4 * u + 3) * 768] = v1.y;
    }
}

// ---------------------------------------------------------------- kernel 3: reduce + bias + sigmoid
// 384 blocks x 256 threads, 1 scalar/thread, 12 independent LDGs (MLP 12)
__global__ void __launch_bounds__(256) k_reduce(const float* __restrict__ bf,
                                                float* __restrict__ y) {
    const int i = blockIdx.x * 256 + threadIdx.x;  // 0..98303
    int o = i % 768;
    float v[12];
#pragma unroll
    for (int k = 0; k < 12; k++) v[k] = __ldg(g_part + (size_t)k * 98304 + i);
    float s01 = v[0] + v[1], s23 = v[2] + v[3], s45 = v[4] + v[5];
    float s67 = v[6] + v[7], s89 = v[8] + v[9], sab = v[10] + v[11];
    float s = ((s01 + s23) + (s45 + s67)) + ((s89 + sab) + __ldg(bf + o));
    y[i] = sig_fast(s);
}

// ---------------------------------------------------------------- launch
extern "C" void kernel_launch(void* const* d_in, const int* in_sizes, int n_in,
                              void* d_out, int out_size) {
    const float* x    = (const float*)d_in[0];  // (128, 768)
    const float* W    = (const float*)d_in[1];  // (3, 768, 768)
    const float* b    = (const float*)d_in[2];  // (3, 768)
    const float* lam  = (const float*)d_in[3];  // (3,)
    const float* eta0 = (const float*)d_in[4];  // (768, 768)
    const float* eta1 = (const float*)d_in[5];  // scalar
    const float* eta2 = (const float*)d_in[6];  // (768, 768)
    const float* wf   = (const float*)d_in[7];  // (768, 2304)
    const float* bf   = (const float*)d_in[8];  // (768,)
    const float* P0   = (const float*)d_in[9];  // (3, 768, 768)
    float* y = (float*)d_out;                   // (128, 768)

    k_scan<<<144, 512>>>(x, W, b, lam, eta0, eta1, eta2, P0, wf);
    k_gemm<<<dim3(3, 4, 12), 256>>>();
    k_reduce<<<384, 256>>>(bf, y);
}

// round 8
// speedup vs baseline: 1.0986x; 1.0986x over previous
#include <cuda_runtime.h>
#include <cstddef>

#define FULLMASK 0xffffffffu
typedef unsigned long long u64;

// T=128, D=768, HID=768, L=3, OUT=768, LH=2304
__device__ float g_H[128 * 2304];        // h_cat per step
__device__ float g_wfT[2304 * 768];      // transposed w_final
__device__ float g_part[12 * 128 * 768]; // split-K partials

// ---------------------------------------------------------------- helpers
__device__ __forceinline__ unsigned smem_u32(const void* p) {
    unsigned a;
    asm("{ .reg .u64 t; cvta.to.shared.u64 t, %1; cvt.u32.u64 %0, t; }"
        : "=r"(a) : "l"(p));
    return a;
}
__device__ __forceinline__ void cp_async16(unsigned d, const void* src) {
    asm volatile("cp.async.ca.shared.global [%0], [%1], 16;\n" :: "r"(d), "l"(src));
}
__device__ __forceinline__ void cp_commit() { asm volatile("cp.async.commit_group;\n" ::); }
__device__ __forceinline__ void cp_wait0()  { asm volatile("cp.async.wait_group 0;\n" ::); }

__device__ __forceinline__ u64 fma2(u64 a, u64 b, u64 c) {
    u64 d; asm("fma.rn.f32x2 %0, %1, %2, %3;" : "=l"(d) : "l"(a), "l"(b), "l"(c)); return d;
}
__device__ __forceinline__ u64 mul2(u64 a, u64 b) {
    u64 d; asm("mul.rn.f32x2 %0, %1, %2;" : "=l"(d) : "l"(a), "l"(b)); return d;
}
__device__ __forceinline__ u64 add2(u64 a, u64 b) {
    u64 d; asm("add.rn.f32x2 %0, %1, %2;" : "=l"(d) : "l"(a), "l"(b)); return d;
}
__device__ __forceinline__ u64 pk2(float x, float y) {
    u64 d; asm("mov.b64 %0, {%1, %2};" : "=l"(d) : "f"(x), "f"(y)); return d;
}
__device__ __forceinline__ float2 up2(u64 v) {
    float2 r; asm("mov.b64 {%0, %1}, %2;" : "=f"(r.x), "=f"(r.y) : "l"(v)); return r;
}
__device__ __forceinline__ void lds2(u64& a, u64& b, unsigned addr) {
    asm volatile("ld.shared.v2.b64 {%0, %1}, [%2];" : "=l"(a), "=l"(b) : "r"(addr));
}
__device__ __forceinline__ void ldg2(u64& a, u64& b, const float* p) {
    asm volatile("ld.global.nc.v2.b64 {%0, %1}, [%2];" : "=l"(a), "=l"(b) : "l"(p));
}
__device__ __forceinline__ float sig_fast(float z) {
    float e = __expf(-z);
    return __fdividef(1.0f, 1.0f + e);
}
// packed pair reduction: 5 stages x (2 shfl.b32 + 1 add.f32x2)
__device__ __forceinline__ u64 wredsum2(u64 v) {
#pragma unroll
    for (int m = 16; m >= 1; m >>= 1) {
        unsigned lo, hi;
        asm volatile("mov.b64 {%0, %1}, %2;" : "=r"(lo), "=r"(hi) : "l"(v));
        lo = __shfl_xor_sync(FULLMASK, lo, m);
        hi = __shfl_xor_sync(FULLMASK, hi, m);
        u64 o; asm volatile("mov.b64 %0, {%1, %2};" : "=l"(o) : "r"(lo), "r"(hi));
        v = add2(v, o);
    }
    return v;
}
__device__ __forceinline__ float hsum(u64 v) { float2 f = up2(v); return f.x + f.y; }

// ---------------------------------------------------------------- shared memory
struct ScanSmem { float wxb[2048]; __align__(16) float xb[2 * 4 * 768]; };  // 32.7KB
union Smem {
    ScanSmem s;
    float tile[64 * 65];          // transpose prologue
};

// ---------------------------------------------------------------- kernel 1: transpose prologue + scan
// 144 CTAs x 256 threads. CTA j: layer l=j/48, rows [(j%48)*16,+16).
// Warp w owns rows 2w,2w+1; lane owns cols {4*lane+128*kk+q : kk<6}.
__global__ void __launch_bounds__(256, 1) k_scan(
    const float* __restrict__ x_seq, const float* __restrict__ W,
    const float* __restrict__ b, const float* __restrict__ lam,
    const float* __restrict__ eta0, const float* __restrict__ eta1p,
    const float* __restrict__ eta2, const float* __restrict__ P_init,
    const float* __restrict__ wf)
{
    __shared__ Smem sm;
    const int tid = threadIdx.x;
    const int bid = blockIdx.x;

    // ---- prologue: wf transpose, 3 tiles of 64x64 per CTA (432 total)
    {
        const int rr = tid >> 4, cc = (tid & 15) * 4;
#pragma unroll 1
        for (int it = 0; it < 3; it++) {
            const int tt = bid * 3 + it;
            const int o0 = (tt % 12) * 64;
            const int j0 = (tt / 12) * 64;
#pragma unroll
            for (int i = 0; i < 4; i++) {
                int r = rr + 16 * i;
                float4 v = *(const float4*)(wf + (size_t)(o0 + r) * 2304 + j0 + cc);
                sm.tile[r * 65 + cc + 0] = v.x; sm.tile[r * 65 + cc + 1] = v.y;
                sm.tile[r * 65 + cc + 2] = v.z; sm.tile[r * 65 + cc + 3] = v.w;
            }
            __syncthreads();
#pragma unroll
            for (int i = 0; i < 4; i++) {
                int jj = rr + 16 * i;
                float4 v;
                v.x = sm.tile[(cc + 0) * 65 + jj];
                v.y = sm.tile[(cc + 1) * 65 + jj];
                v.z = sm.tile[(cc + 2) * 65 + jj];
                v.w = sm.tile[(cc + 3) * 65 + jj];
                *(float4*)(g_wfT + (size_t)(j0 + jj) * 768 + o0 + cc) = v;
            }
            __syncthreads();
        }
    }

    // ---- scan setup
    const int l  = bid / 48;
    const int rb = (bid % 48) * 16;
    const int w = tid >> 5, lane = tid & 31;
    const int r0 = 2 * w;
    const int gr0 = rb + r0, gr1 = gr0 + 1;
    const float* Wl = W + (size_t)l * 589824;
    const int cb = 4 * lane;
    float* wxb = sm.s.wxb;

    // ---- WXB precompute: wxb[t][r] = W[r,:]@x_t + b[r]
    {
        u64 wv0[12], wv1[12];
#pragma unroll
        for (int kk = 0; kk < 6; kk++) {
            ldg2(wv0[2 * kk], wv0[2 * kk + 1], Wl + (size_t)gr0 * 768 + cb + 128 * kk);
            ldg2(wv1[2 * kk], wv1[2 * kk + 1], Wl + (size_t)gr1 * 768 + cb + 128 * kk);
        }
        const float bb0 = b[l * 768 + gr0], bb1 = b[l * 768 + gr1];

        float4* xf4 = (float4*)sm.s.xb;
        const float4* xs4 = (const float4*)x_seq;
        const unsigned xfs = smem_u32(sm.s.xb);
        for (int c0 = 0; c0 < 128; c0 += 8) {
#pragma unroll
            for (int i = 0; i < 6; i++)
                xf4[tid + 256 * i] = xs4[(size_t)c0 * 192 + tid + 256 * i];
            __syncthreads();
#pragma unroll
            for (int tt = 0; tt < 8; tt++) {
                const unsigned xa = xfs + tt * 3072 + 16 * lane;
                u64 a0 = 0, a1 = 0, a2 = 0, a3 = 0;
#pragma unroll
                for (int kk = 0; kk < 6; kk++) {
                    u64 x0, x1; lds2(x0, x1, xa + 512 * kk);
                    a0 = fma2(wv0[2 * kk], x0, a0); a2 = fma2(wv0[2 * kk + 1], x1, a2);
                    a1 = fma2(wv1[2 * kk], x0, a1); a3 = fma2(wv1[2 * kk + 1], x1, a3);
                }
                u64 s01 = wredsum2(pk2(hsum(add2(a0, a2)), hsum(add2(a1, a3))));
                if (lane == 0) {
                    float2 s = up2(s01);
                    wxb[(c0 + tt) * 16 + r0]     = s.x + bb0;
                    wxb[(c0 + tt) * 16 + r0 + 1] = s.y + bb1;
                }
            }
            __syncthreads();
        }
    }

    // ---- persistent state (unified A/M): A: q=P, e=eta, escal=1 | M: q=W.P, e=W, escal=eta1
    u64 q0[12], q1[12], e0[12], e1[12];
    const float* Pl = P_init + (size_t)l * 589824;
#pragma unroll
    for (int kk = 0; kk < 6; kk++) {
        ldg2(q0[2 * kk], q0[2 * kk + 1], Pl + (size_t)gr0 * 768 + cb + 128 * kk);
        ldg2(q1[2 * kk], q1[2 * kk + 1], Pl + (size_t)gr1 * 768 + cb + 128 * kk);
    }
    const float* ep = (l == 0) ? eta0 : ((l == 2) ? eta2 : Wl);
#pragma unroll
    for (int kk = 0; kk < 6; kk++) {
        ldg2(e0[2 * kk], e0[2 * kk + 1], ep + (size_t)gr0 * 768 + cb + 128 * kk);
        ldg2(e1[2 * kk], e1[2 * kk + 1], ep + (size_t)gr1 * 768 + cb + 128 * kk);
    }
    if (l == 1) {
#pragma unroll
        for (int k = 0; k < 12; k++) { q0[k] = mul2(q0[k], e0[k]); q1[k] = mul2(q1[k], e1[k]); }
    }
    const float decay = 1.0f / (1.0f + __expf(-lam[l]));
    const float escal = (l == 1) ? eta1p[0] : 1.0f;
    const float d2v = decay * decay;
    const float a0c = decay * escal;          // coef for h0 in update
    const u64 d2p = pk2(d2v, d2v);
    const int gc0 = l * 768 + rb + r0;
    const unsigned xbs = smem_u32(sm.s.xb);

    // ---- preload chunk 0 (4 steps = 3072 floats)
#pragma unroll
    for (int i = 0; i < 3; i++)
        cp_async16(xbs + 16 * (tid + 256 * i), x_seq + 4 * (tid + 256 * i));
    cp_commit(); cp_wait0();
    __syncthreads();

    // ---- the scan: 32 chunks x (2 batches of 2 steps)
    for (int c = 0; c < 32; c++) {
        if (c < 31) {
            const float* src = x_seq + (size_t)(c + 1) * 3072;
            unsigned dst = xbs + ((c + 1) & 1) * 12288;
#pragma unroll
            for (int i = 0; i < 3; i++)
                cp_async16(dst + 16 * (tid + 256 * i), src + 4 * (tid + 256 * i));
            cp_commit();
        }
        const unsigned xcs = xbs + (c & 1) * 12288;
#pragma unroll
        for (int half = 0; half < 2; half++) {
            const int t = c * 4 + half * 2;
            const unsigned xa0 = xcs + (half * 2) * 3072 + 16 * lane;
            u64 x0[12], x1[12];
#pragma unroll
            for (int kk = 0; kk < 6; kk++) {
                lds2(x0[2 * kk], x0[2 * kk + 1], xa0 + 512 * kk);
                lds2(x1[2 * kk], x1[2 * kk + 1], xa0 + 3072 + 512 * kk);
            }
            // 6 independent dots (all h-independent): u0,u1 per row + v per row
            u64 au00 = 0, au10 = 0, au01 = 0, au11 = 0, av0 = 0, av1 = 0;
#pragma unroll
            for (int k = 0; k < 12; k++) {
                u64 wk = mul2(x0[k], x1[k]);
                au00 = fma2(q0[k], x0[k], au00);
                au10 = fma2(q0[k], x1[k], au10);
                au01 = fma2(q1[k], x0[k], au01);
                au11 = fma2(q1[k], x1[k], au11);
                av0  = fma2(e0[k], wk, av0);
                av1  = fma2(e1[k], wk, av1);
            }
            // packed reductions: A=(u0,u1) row0; B=(u0,u1) row1; C=(v0,v1)
            u64 A = wredsum2(pk2(hsum(au00), hsum(au10)));
            u64 B = wredsum2(pk2(hsum(au01), hsum(au11)));
            u64 C = wredsum2(pk2(hsum(av0),  hsum(av1)));
            float2 fa = up2(A), fb = up2(B), fc = up2(C);
            const float2 wx0 = *(const float2*)(wxb + t * 16 + r0);
            const float2 wx1 = *(const float2*)(wxb + (t + 1) * 16 + r0);
            // h0 = sig(u0 + wxb); h1 = sig(decay*u1 + escal*h0*v + wxb')
            float h00 = sig_fast(fa.x + wx0.x);
            float h01 = sig_fast(fb.x + wx0.y);
            float h10 = sig_fast(fmaf(decay, fa.y, fmaf(escal * h00, fc.x, wx1.x)));
            float h11 = sig_fast(fmaf(decay, fb.y, fmaf(escal * h01, fc.y, wx1.y)));
            if (lane == 0) {
                float2 hv0; hv0.x = h00; hv0.y = h01;
                float2 hv1; hv1.x = h10; hv1.y = h11;
                *(float2*)(g_H + (size_t)t * 2304 + gc0) = hv0;
                *(float2*)(g_H + (size_t)(t + 1) * 2304 + gc0) = hv1;
            }
            // batched update: q = d2*q + e .* (a0*x0 + a1*x1)
            const u64 p00 = pk2(a0c * h00, a0c * h00);
            const u64 p10 = pk2(escal * h10, escal * h10);
            const u64 p01 = pk2(a0c * h01, a0c * h01);
            const u64 p11 = pk2(escal * h11, escal * h11);
#pragma unroll
            for (int k = 0; k < 12; k++) {
                u64 z0 = fma2(p10, x1[k], mul2(p00, x0[k]));
                q0[k] = fma2(e0[k], z0, mul2(q0[k], d2p));
                u64 z1 = fma2(p11, x1[k], mul2(p01, x0[k]));
                q1[k] = fma2(e1[k], z1, mul2(q1[k], d2p));
            }
        }
        if (c < 31) cp_wait0();
        __syncthreads();
    }
}

// ---------------------------------------------------------------- kernel 2: readout GEMM (split-K 12)
__global__ void __launch_bounds__(256) k_gemm() {
    __shared__ __align__(16) float Hs[192 * 36];  // [192 j][32 t + pad 4]
    const int ob = blockIdx.x, tb = blockIdx.y, kb = blockIdx.z;
    const int tid = threadIdx.x;
    const int t0 = tb * 32;
#pragma unroll
    for (int i = 0; i < 24; i++) {
        int idx = tid + 256 * i;
        int tl = idx / 192, jl = idx - tl * 192;
        Hs[jl * 36 + tl] = g_H[(size_t)(t0 + tl) * 2304 + kb * 192 + jl];
    }
    __syncthreads();

    u64 acc[16];
#pragma unroll
    for (int i = 0; i < 16; i++) acc[i] = 0;

    const int o = ob * 256 + tid;
    const float* wp = g_wfT + (size_t)(kb * 192) * 768 + o;
    const unsigned hs = smem_u32(Hs);
#pragma unroll 8
    for (int j = 0; j < 192; j++) {
        float wv = __ldg(wp + (size_t)j * 768);
        u64 w2 = pk2(wv, wv);
        const unsigned ha = hs + j * 144;
#pragma unroll
        for (int u = 0; u < 8; u++) {
            u64 h0, h1; lds2(h0, h1, ha + 16 * u);
            acc[2 * u]     = fma2(w2, h0, acc[2 * u]);
            acc[2 * u + 1] = fma2(w2, h1, acc[2 * u + 1]);
        }
    }
    float* pp = g_part + (size_t)kb * 98304 + (size_t)t0 * 768 + o;
#pragma unroll
    for (int u = 0; u < 8; u++) {
        float2 v0 = up2(acc[2 * u]), v1 = up2(acc[2 * u + 1]);
        pp[(size_t)(4 * u + 0) * 768] = v0.x;
        pp[(size_t)(4 * u + 1) * 768] = v0.y;
        pp[(size_t)(4 * u + 2) * 768] = v1.x;
        pp[(size_t)(4 * u + 3) * 768] = v1.y;
    }
}

// ---------------------------------------------------------------- kernel 3: reduce + bias + sigmoid
// 384 blocks x 256 threads, 1 scalar/thread, 12 independent LDGs (MLP 12)
__global__ void __launch_bounds__(256) k_reduce(const float* __restrict__ bf,
                                                float* __restrict__ y) {
    const int i = blockIdx.x * 256 + threadIdx.x;  // 0..98303
    int o = i % 768;
    float v[12];
#pragma unroll
    for (int k = 0; k < 12; k++) v[k] = __ldg(g_part + (size_t)k * 98304 + i);
    float s01 = v[0] + v[1], s23 = v[2] + v[3], s45 = v[4] + v[5];
    float s67 = v[6] + v[7], s89 = v[8] + v[9], sab = v[10] + v[11];
    float s = ((s01 + s23) + (s45 + s67)) + ((s89 + sab) + __ldg(bf + o));
    y[i] = sig_fast(s);
}

// ---------------------------------------------------------------- launch
extern "C" void kernel_launch(void* const* d_in, const int* in_sizes, int n_in,
                              void* d_out, int out_size) {
    const float* x    = (const float*)d_in[0];  // (128, 768)
    const float* W    = (const float*)d_in[1];  // (3, 768, 768)
    const float* b    = (const float*)d_in[2];  // (3, 768)
    const float* lam  = (const float*)d_in[3];  // (3,)
    const float* eta0 = (const float*)d_in[4];  // (768, 768)
    const float* eta1 = (const float*)d_in[5];  // scalar
    const float* eta2 = (const float*)d_in[6];  // (768, 768)
    const float* wf   = (const float*)d_in[7];  // (768, 2304)
    const float* bf   = (const float*)d_in[8];  // (768,)
    const float* P0   = (const float*)d_in[9];  // (3, 768, 768)
    float* y = (float*)d_out;                   // (128, 768)

    k_scan<<<144, 256>>>(x, W, b, lam, eta0, eta1, eta2, P0, wf);
    k_gemm<<<dim3(3, 4, 12), 256>>>();
    k_reduce<<<384, 256>>>(bf, y);
}